// round 17
// baseline (speedup 1.0000x reference)
#include <cuda_runtime.h>
#include <cstdint>
#include <math.h>

#define BB 32
#define DD 1024
#define HH 64
#define OO 1000
#define EE 6
#define NBLK 128
#define NTHR 512
#define CLUSTER 4

__device__ __forceinline__ void fma4(float4& acc, float v, const float4& w) {
    acc.x += v * w.x; acc.y += v * w.y; acc.z += v * w.z; acc.w += v * w.w;
}

__global__ void __launch_bounds__(NTHR, 1) __cluster_dims__(CLUSTER, 1, 1)
moe_fused(const float* __restrict__ x,
          const float* __restrict__ gw,
          const float* __restrict__ gb,
          const float* __restrict__ w1,
          const float* __restrict__ b1,
          const float* __restrict__ w2,
          const float* __restrict__ b2,
          float* __restrict__ out) {
    const int bid = blockIdx.x;
    const int tid = threadIdx.x;
    const int warp = tid >> 5, lane = tid & 31;

    __shared__ __align__(16) float part[16][32];    // fc1 cross-warp partials
    __shared__ __align__(16) float hs[32];          // this block's h cols (gate-scaled)
    __shared__ float logit[EE];

    // Cluster = the 4 blocks of row b; roles: expert slot k, col-half ch.
    const int b = bid >> 2, j = bid & 3;
    const int k = j >> 1, ch = j & 1;

    // ---- zero my quarter of out[b,:], then non-blocking cluster arrive -----
    if (tid < 250) out[b * OO + j * 250 + tid] = 0.0f;
    asm volatile("barrier.cluster.arrive.aligned;" ::: "memory");

    // ---- x chunk straight to registers (16 d per thread) -------------------
    const int dg = tid >> 3, cg = tid & 7;          // 64 d-groups x 8 col-groups
    float4 xr4[4];
    {
        const float4* xcp = (const float4*)(x + b * DD + dg * 16);
        #pragma unroll
        for (int i = 0; i < 4; ++i) xr4[i] = __ldg(xcp + i);
    }

    // ---- gate logits from global x -----------------------------------------
    if (warp < EE) {
        const float* xr = x + b * DD;
        float s0 = 0.f, s1 = 0.f, s2 = 0.f, s3 = 0.f;
        #pragma unroll
        for (int i = 0; i < DD / 128; ++i) {        // 4-way chain split
            int d = lane + 128 * i;
            s0 += xr[d]      * gw[(d)      * EE + warp];
            s1 += xr[d + 32] * gw[(d + 32) * EE + warp];
            s2 += xr[d + 64] * gw[(d + 64) * EE + warp];
            s3 += xr[d + 96] * gw[(d + 96) * EE + warp];
        }
        float s = (s0 + s1) + (s2 + s3);
        #pragma unroll
        for (int off = 16; off > 0; off >>= 1)
            s += __shfl_down_sync(0xFFFFFFFFu, s, off);
        if (lane == 0) logit[warp] = s + gb[warp];
    }
    __syncthreads();                                // publishes the 6 logits

    // ---- top-2 + 2-way softmax (every thread; registers only) -------------
    float v[EE];
    #pragma unroll
    for (int e = 0; e < EE; ++e) v[e] = logit[e];
    int i1 = 0; float m1 = v[0];
    #pragma unroll
    for (int e = 1; e < EE; ++e) if (v[e] > m1) { m1 = v[e]; i1 = e; }
    int i2 = -1; float m2 = -INFINITY;
    #pragma unroll
    for (int e = 0; e < EE; ++e) if (e != i1 && v[e] > m2) { m2 = v[e]; i2 = e; }
    const float g1 = 1.0f / (1.0f + __expf(m2 - m1));   // m1 >= m2: stable
    const float gk = (k == 0) ? g1 : (1.0f - g1);
    const int   e  = (k == 0) ? i1 : i2;

    // Prefetch fc1 bias early (consumed after the reduce)
    const float biasv = __ldg(&b1[e * HH + ch * 32 + (tid & 31)]);

    // ---- fc1 (32 cols of half ch): x regs, w1 global, 16 d per thread ------
    float4 t;
    {
        const float* wbase = w1 + ((size_t)e * DD + dg * 16) * HH + ch * 32 + cg * 4;
        float4 a0 = {0,0,0,0}, a1 = {0,0,0,0}, a2 = {0,0,0,0}, a3 = {0,0,0,0};
        #pragma unroll
        for (int d4 = 0; d4 < 4; ++d4) {
            const float4 xv = xr4[d4];
            fma4(a0, xv.x, *(const float4*)(wbase + (d4 * 4 + 0) * HH));
            fma4(a1, xv.y, *(const float4*)(wbase + (d4 * 4 + 1) * HH));
            fma4(a2, xv.z, *(const float4*)(wbase + (d4 * 4 + 2) * HH));
            fma4(a3, xv.w, *(const float4*)(wbase + (d4 * 4 + 3) * HH));
        }
        t.x = (a0.x + a1.x) + (a2.x + a3.x);
        t.y = (a0.y + a1.y) + (a2.y + a3.y);
        t.z = (a0.z + a1.z) + (a2.z + a3.z);
        t.w = (a0.w + a1.w) + (a2.w + a3.w);
    }

    // ---- prefetch w2: MY expert, MY 16 k-cols, outputs 4q..4q+3 ------------
    const int q = (tid >> 1 < 250) ? (tid >> 1) : 249;  // output quad (clamped)
    const int s = tid & 1;                              // k-half (16 k each)
    float4 w2r[16];
    {
        const float* wp = w2 + ((size_t)e * HH + ch * 32 + s * 16) * OO + q * 4;
        #pragma unroll
        for (int c = 0; c < 16; ++c)
            w2r[c] = __ldg((const float4*)(wp + c * OO));
    }
    float4 bb = {0, 0, 0, 0};
    if (ch == 0 && s == 0) bb = __ldg((const float4*)(b2 + (size_t)e * OO + q * 4));

    // ---- finish fc1: fold 4 dg-groups in-warp, then 16-deep smem reduce ----
    // warp holds dg = 4*warp + (lane>>3); fold offsets 16, 8
    #pragma unroll
    for (int off = 16; off >= 8; off >>= 1) {
        t.x += __shfl_xor_sync(0xFFFFFFFFu, t.x, off);
        t.y += __shfl_xor_sync(0xFFFFFFFFu, t.y, off);
        t.z += __shfl_xor_sync(0xFFFFFFFFu, t.z, off);
        t.w += __shfl_xor_sync(0xFFFFFFFFu, t.w, off);
    }
    if (lane < 8) *(float4*)&part[warp][lane * 4] = t;
    __syncthreads();
    if (tid < 32) {
        float sum = biasv;
        #pragma unroll
        for (int w = 0; w < 16; ++w) sum += part[w][tid];
        hs[tid] = gk * fmaxf(sum, 0.0f);            // gate pre-applied, LOCAL only
    }
    __syncthreads();

    // ---- fc2 partial: my 16 k-cols x my 4 outputs (h broadcast from smem) --
    float4 a0 = {0,0,0,0}, a1 = {0,0,0,0}, a2 = {0,0,0,0}, a3 = {0,0,0,0};
    const float* hp = hs + s * 16;
    #pragma unroll
    for (int c = 0; c < 16; c += 4) {
        fma4(a0, hp[c + 0], w2r[c + 0]);
        fma4(a1, hp[c + 1], w2r[c + 1]);
        fma4(a2, hp[c + 2], w2r[c + 2]);
        fma4(a3, hp[c + 3], w2r[c + 3]);
    }
    float4 acc;
    acc.x = (a0.x + a1.x) + (a2.x + a3.x);
    acc.y = (a0.y + a1.y) + (a2.y + a3.y);
    acc.z = (a0.z + a1.z) + (a2.z + a3.z);
    acc.w = (a0.w + a1.w) + (a2.w + a3.w);

    // combine the two k-halves (pair lanes 2q, 2q+1 share a warp)
    acc.x += __shfl_xor_sync(0xFFFFFFFFu, acc.x, 1);
    acc.y += __shfl_xor_sync(0xFFFFFFFFu, acc.y, 1);
    acc.z += __shfl_xor_sync(0xFFFFFFFFu, acc.z, 1);
    acc.w += __shfl_xor_sync(0xFFFFFFFFu, acc.w, 1);

    if (ch == 0 && s == 0) {                        // gate-weighted bias once per slot
        acc.x += gk * bb.x; acc.y += gk * bb.y;
        acc.z += gk * bb.z; acc.w += gk * bb.w;
    }

    // ---- wait for cluster-mates' zeroing (arrived ages ago: fast-path) -----
    asm volatile("barrier.cluster.wait.aligned;" ::: "memory");

    // ---- accumulate into out: 4 commutative adds per element ---------------
    if (s == 0 && (tid >> 1) < 250) {
        float* op = out + b * OO + q * 4;
        atomicAdd(op + 0, acc.x);
        atomicAdd(op + 1, acc.y);
        atomicAdd(op + 2, acc.z);
        atomicAdd(op + 3, acc.w);
    }
}

// Inputs: x, gate_w, gate_b, w1, b1, w2, b2. Output: f32 [32,1000]
extern "C" void kernel_launch(void* const* d_in, const int* in_sizes, int n_in,
                              void* d_out, int out_size) {
    const float* x  = (const float*)d_in[0];
    const float* gw = (const float*)d_in[1];
    const float* gb = (const float*)d_in[2];
    const float* w1 = (const float*)d_in[3];
    const float* b1 = (const float*)d_in[4];
    const float* w2 = (const float*)d_in[5];
    const float* b2 = (const float*)d_in[6];
    float* out = (float*)d_out;

    moe_fused<<<NBLK, NTHR>>>(x, gw, gb, w1, b1, w2, b2, out);
}